// round 16
// baseline (speedup 1.0000x reference)
#include <cuda_runtime.h>
#include <stdint.h>

#define L_EXP 16
#define IN0   7
#define C0    16
#define C1    32
#define C2    16
#define NEG   0.2f
#define TPB   256
#define PPT   2
#define PPB   (TPB * PPT)        // 512

#define SEG_SHIFT 16
#define SEG       (1 << SEG_SHIFT)          // 65536 slots per expert
#define WORK_CAP  4096

__device__ int    g_cursor[L_EXP] = {
    0, 65536, 131072, 196608, 262144, 327680, 393216, 458752,
    524288, 589824, 655360, 720896, 786432, 851968, 917504, 983040
};
__device__ int    g_done = 0;
__device__ int    g_cnt[L_EXP];
__device__ int    g_nwork = 0;
__device__ int    g_work[WORK_CAP];
__device__ int    g_perm[L_EXP * SEG];          // 4 MB
__device__ float4 g_xb[L_EXP * SEG * 2];        // 32 MB

// ---------------- packed f32x2 FMA ----------------
union F2U { float2 f; unsigned long long u; };
__device__ __forceinline__ float2 ffma2(float2 a, float2 b, float2 c) {
    F2U ua, ub, uc, ud;
    ua.f = a; ub.f = b; uc.f = c;
    asm("fma.rn.f32x2 %0, %1, %2, %3;" : "=l"(ud.u) : "l"(ua.u), "l"(ub.u), "l"(uc.u));
    return ud.f;
}
__device__ __forceinline__ float lrelu(float v) { return fmaxf(v, NEG * v); }

// ---------------- pass 1: bin + x copy (2 pts/thread) + tail builds work list ----------------
__global__ __launch_bounds__(TPB)
void k_scatter(const int* __restrict__ idx,
               const float* __restrict__ x, int n, int nblk) {
    __shared__ int scnt[L_EXP];
    __shared__ int sbase[L_EXP];
    __shared__ int s_last;
    __shared__ int s_pref[L_EXP + 1];
    const int t = threadIdx.x;
    if (t < L_EXP) scnt[t] = 0;
    __syncthreads();

    const int p0 = (blockIdx.x * TPB + t) * 2;

    int e[2] = {-1, -1}, r[2];
    if (p0 + 1 < n) {
        int2 v = *(const int2*)(idx + p0);
        e[0] = v.x; e[1] = v.y;
    } else if (p0 < n) {
        e[0] = idx[p0];
    }

    float f[14];
    if (p0 + 1 < n) {
        const float2* xv = (const float2*)(x + (size_t)p0 * IN0);
        #pragma unroll
        for (int k = 0; k < 7; k++) {
            float2 v = xv[k];
            f[2*k] = v.x; f[2*k+1] = v.y;
        }
    } else if (p0 < n) {
        #pragma unroll
        for (int i = 0; i < IN0; i++) f[i] = x[(size_t)p0 * IN0 + i];
    }

    #pragma unroll
    for (int k = 0; k < 2; k++)
        if (e[k] >= 0) r[k] = atomicAdd(&scnt[e[k]], 1);
    __syncthreads();
    if (t < L_EXP) sbase[t] = (scnt[t] > 0) ? atomicAdd(&g_cursor[t], scnt[t]) : 0;
    __syncthreads();

    #pragma unroll
    for (int k = 0; k < 2; k++) {
        if (e[k] >= 0) {
            const int slot = sbase[e[k]] + r[k];
            if (slot < ((e[k] + 1) << SEG_SHIFT)) {
                g_perm[slot] = p0 + k;
                g_xb[2*slot]   = make_float4(f[7*k],   f[7*k+1], f[7*k+2], f[7*k+3]);
                g_xb[2*slot+1] = make_float4(f[7*k+4], f[7*k+5], f[7*k+6], 0.f);
            }
        }
    }

    // ---- tail: last block snapshots counts, resets cursors, builds work list ----
    if (t == 0) {
        __threadfence();
        s_last = (atomicAdd(&g_done, 1) == nblk - 1) ? 1 : 0;
    }
    __syncthreads();
    if (s_last) {
        if (t < L_EXP) {
            int c = g_cursor[t] - (t << SEG_SHIFT);
            if (c > SEG) c = SEG;
            g_cnt[t] = c;
            g_cursor[t] = t << SEG_SHIFT;
            s_pref[t] = (c + PPB - 1) / PPB;
        }
        __syncthreads();
        if (t == 0) {
            int acc = 0;
            #pragma unroll
            for (int k = 0; k < L_EXP; k++) { int nb = s_pref[k]; s_pref[k] = acc; acc += nb; }
            s_pref[L_EXP] = acc;
            g_nwork = acc;
            g_done = 0;
        }
        __syncthreads();
        if (t < L_EXP) {
            const int start = s_pref[t];
            const int nb    = s_pref[t + 1] - start;
            for (int b = 0; b < nb; b++) g_work[start + b] = (t << 8) | b;
        }
    }
}

// ---------------- pass 2: block-uniform-expert MLP, 2 pts/thread (R12 body, hoisted x loads) ----------------
__global__ __launch_bounds__(TPB)
void k_main(const float* __restrict__ W0, const float* __restrict__ b0,
            const float* __restrict__ W1, const float* __restrict__ b1,
            const float* __restrict__ W2, const float* __restrict__ b2,
            float* __restrict__ out)
{
    __shared__ __align__(16) float sW0[IN0 * C0];
    __shared__ __align__(16) float sW1[C0 * C1];
    __shared__ __align__(16) float sW2[C1 * C2];
    __shared__ __align__(16) float sB0[C0];
    __shared__ __align__(16) float sB1[C1];
    __shared__ __align__(16) float sB2[C2];

    if ((int)blockIdx.x >= g_nwork) return;
    const int w          = g_work[blockIdx.x];
    const int e          = w >> 8;
    const int local_base = (w & 0xff) * PPB;
    const int cnt        = g_cnt[e];

    const int t = threadIdx.x;
    const int seg0 = (e << SEG_SHIFT) + local_base;

    // ---- issue x loads FIRST: latency hides behind weight staging + barrier ----
    bool valid[PPT];
    float h0[PPT][7];
    #pragma unroll
    for (int q = 0; q < PPT; q++) {
        valid[q] = (local_base + t + q * TPB) < cnt;
        const int slot = seg0 + t + q * TPB;
        if (valid[q]) {
            float4 a = g_xb[2 * slot];
            float4 b = g_xb[2 * slot + 1];
            h0[q][0]=a.x; h0[q][1]=a.y; h0[q][2]=a.z; h0[q][3]=a.w;
            h0[q][4]=b.x; h0[q][5]=b.y; h0[q][6]=b.z;
        } else {
            #pragma unroll
            for (int i = 0; i < 7; i++) h0[q][i] = 0.f;
        }
    }

    const float* W0e = W0 + e * IN0 * C0;
    const float* W1e = W1 + e * C0 * C1;
    const float* W2e = W2 + e * C1 * C2;
    for (int d = t; d < IN0 * C0; d += TPB) sW0[d] = W0e[d];
    for (int d = t; d < C0 * C1;  d += TPB) sW1[d] = W1e[d];
    for (int d = t; d < C1 * C2;  d += TPB) sW2[d] = W2e[d];
    if (t < C0) sB0[t] = b0[e * C0 + t];
    if (t < C1) sB1[t] = b1[e * C1 + t];
    if (t < C2) sB2[t] = b2[e * C2 + t];
    __syncthreads();

    // ---- layer 0: 7 -> 16 ----
    float2 a0[PPT][C0 / 2];
    #pragma unroll
    for (int o = 0; o < C0 / 2; o++) {
        float2 bv = ((const float2*)sB0)[o];
        a0[0][o] = bv; a0[1][o] = bv;
    }
    #pragma unroll
    for (int i = 0; i < IN0; i++) {
        float2 hA = make_float2(h0[0][i], h0[0][i]);
        float2 hB = make_float2(h0[1][i], h0[1][i]);
        #pragma unroll
        for (int q4 = 0; q4 < C0 / 4; q4++) {
            float4 w4 = *(const float4*)&sW0[i * C0 + 4 * q4];
            float2 w01 = make_float2(w4.x, w4.y), w23 = make_float2(w4.z, w4.w);
            a0[0][2*q4]   = ffma2(hA, w01, a0[0][2*q4]);
            a0[0][2*q4+1] = ffma2(hA, w23, a0[0][2*q4+1]);
            a0[1][2*q4]   = ffma2(hB, w01, a0[1][2*q4]);
            a0[1][2*q4+1] = ffma2(hB, w23, a0[1][2*q4+1]);
        }
    }
    float h1[PPT][C0];
    #pragma unroll
    for (int q = 0; q < PPT; q++)
        #pragma unroll
        for (int o = 0; o < C0 / 2; o++) {
            h1[q][2*o]   = lrelu(a0[q][o].x);
            h1[q][2*o+1] = lrelu(a0[q][o].y);
        }

    // ---- layer 1: 16 -> 32 ----
    float2 a1[PPT][C1 / 2];
    #pragma unroll
    for (int o = 0; o < C1 / 2; o++) {
        float2 bv = ((const float2*)sB1)[o];
        a1[0][o] = bv; a1[1][o] = bv;
    }
    #pragma unroll
    for (int i = 0; i < C0; i++) {
        float2 hA = make_float2(h1[0][i], h1[0][i]);
        float2 hB = make_float2(h1[1][i], h1[1][i]);
        #pragma unroll
        for (int q4 = 0; q4 < C1 / 4; q4++) {
            float4 w4 = *(const float4*)&sW1[i * C1 + 4 * q4];
            float2 w01 = make_float2(w4.x, w4.y), w23 = make_float2(w4.z, w4.w);
            a1[0][2*q4]   = ffma2(hA, w01, a1[0][2*q4]);
            a1[0][2*q4+1] = ffma2(hA, w23, a1[0][2*q4+1]);
            a1[1][2*q4]   = ffma2(hB, w01, a1[1][2*q4]);
            a1[1][2*q4+1] = ffma2(hB, w23, a1[1][2*q4+1]);
        }
    }
    float h2[PPT][C1];
    #pragma unroll
    for (int q = 0; q < PPT; q++)
        #pragma unroll
        for (int o = 0; o < C1 / 2; o++) {
            h2[q][2*o]   = lrelu(a1[q][o].x);
            h2[q][2*o+1] = lrelu(a1[q][o].y);
        }

    // ---- layer 2: 32 -> 16 ----
    float2 a2[PPT][C2 / 2];
    #pragma unroll
    for (int o = 0; o < C2 / 2; o++) {
        float2 bv = ((const float2*)sB2)[o];
        a2[0][o] = bv; a2[1][o] = bv;
    }
    #pragma unroll
    for (int i = 0; i < C1; i++) {
        float2 hA = make_float2(h2[0][i], h2[0][i]);
        float2 hB = make_float2(h2[1][i], h2[1][i]);
        #pragma unroll
        for (int q4 = 0; q4 < C2 / 4; q4++) {
            float4 w4 = *(const float4*)&sW2[i * C2 + 4 * q4];
            float2 w01 = make_float2(w4.x, w4.y), w23 = make_float2(w4.z, w4.w);
            a2[0][2*q4]   = ffma2(hA, w01, a2[0][2*q4]);
            a2[0][2*q4+1] = ffma2(hA, w23, a2[0][2*q4+1]);
            a2[1][2*q4]   = ffma2(hB, w01, a2[1][2*q4]);
            a2[1][2*q4+1] = ffma2(hB, w23, a2[1][2*q4+1]);
        }
    }

    #pragma unroll
    for (int q = 0; q < PPT; q++) {
        if (valid[q]) {
            const int p = g_perm[seg0 + t + q * TPB];
            float ho[C2];
            #pragma unroll
            for (int o = 0; o < C2 / 2; o++) {
                ho[2*o]   = lrelu(a2[q][o].x);
                ho[2*o+1] = lrelu(a2[q][o].y);
            }
            float4* op = reinterpret_cast<float4*>(out + (size_t)p * C2);
            op[0] = make_float4(ho[0],  ho[1],  ho[2],  ho[3]);
            op[1] = make_float4(ho[4],  ho[5],  ho[6],  ho[7]);
            op[2] = make_float4(ho[8],  ho[9],  ho[10], ho[11]);
            op[3] = make_float4(ho[12], ho[13], ho[14], ho[15]);
        }
    }
}

extern "C" void kernel_launch(void* const* d_in, const int* in_sizes, int n_in,
                              void* d_out, int out_size)
{
    const float* x   = (const float*)d_in[0];
    const int*   idx = (const int*)  d_in[1];
    const float* W0  = (const float*)d_in[2];
    const float* b0  = (const float*)d_in[3];
    const float* W1  = (const float*)d_in[4];
    const float* b1  = (const float*)d_in[5];
    const float* W2  = (const float*)d_in[6];
    const float* b2  = (const float*)d_in[7];
    float* out = (float*)d_out;

    const int n = in_sizes[1];

    const int nblk_s = (n + 2 * TPB - 1) / (2 * TPB);
    k_scatter<<<nblk_s, TPB>>>(idx, x, n, nblk_s);

    int maxwork = (n + PPB - 1) / PPB + L_EXP;
    if (maxwork > WORK_CAP) maxwork = WORK_CAP;
    k_main<<<maxwork, TPB>>>(W0, b0, W1, b1, W2, b2, out);
}

// round 17
// speedup vs baseline: 1.2848x; 1.2848x over previous
#include <cuda_runtime.h>
#include <stdint.h>

#define L_EXP 16
#define IN0   7
#define C0    16
#define C1    32
#define C2    16
#define NEG   0.2f
#define TPB   256
#define PPT   2
#define PPB   (TPB * PPT)        // 512

#define SEG_SHIFT 16
#define SEG       (1 << SEG_SHIFT)          // 65536 slots per expert
#define WORK_CAP  4096

__device__ int    g_cursor[L_EXP] = {
    0, 65536, 131072, 196608, 262144, 327680, 393216, 458752,
    524288, 589824, 655360, 720896, 786432, 851968, 917504, 983040
};
__device__ int    g_done = 0;
__device__ int    g_cnt[L_EXP];
__device__ int    g_nwork = 0;
__device__ int    g_work[WORK_CAP];
__device__ int    g_perm[L_EXP * SEG];          // 4 MB
__device__ float4 g_xb[L_EXP * SEG * 2];        // 32 MB

// ---------------- packed f32x2 FMA ----------------
union F2U { float2 f; unsigned long long u; };
__device__ __forceinline__ float2 ffma2(float2 a, float2 b, float2 c) {
    F2U ua, ub, uc, ud;
    ua.f = a; ub.f = b; uc.f = c;
    asm("fma.rn.f32x2 %0, %1, %2, %3;" : "=l"(ud.u) : "l"(ua.u), "l"(ub.u), "l"(uc.u));
    return ud.f;
}
__device__ __forceinline__ float lrelu(float v) { return fmaxf(v, NEG * v); }

// ---------------- pass 1: bin + x copy (2 pts/thread) + tail builds work list ----------------
__global__ __launch_bounds__(TPB)
void k_scatter(const int* __restrict__ idx,
               const float* __restrict__ x, int n, int nblk) {
    __shared__ int scnt[L_EXP];
    __shared__ int sbase[L_EXP];
    __shared__ int s_last;
    __shared__ int s_pref[L_EXP + 1];
    const int t = threadIdx.x;
    if (t < L_EXP) scnt[t] = 0;
    __syncthreads();

    const int p0 = (blockIdx.x * TPB + t) * 2;

    int e[2] = {-1, -1}, r[2];
    if (p0 + 1 < n) {
        int2 v = *(const int2*)(idx + p0);
        e[0] = v.x; e[1] = v.y;
    } else if (p0 < n) {
        e[0] = idx[p0];
    }

    float f[14];
    if (p0 + 1 < n) {
        const float2* xv = (const float2*)(x + (size_t)p0 * IN0);
        #pragma unroll
        for (int k = 0; k < 7; k++) {
            float2 v = xv[k];
            f[2*k] = v.x; f[2*k+1] = v.y;
        }
    } else if (p0 < n) {
        #pragma unroll
        for (int i = 0; i < IN0; i++) f[i] = x[(size_t)p0 * IN0 + i];
    }

    #pragma unroll
    for (int k = 0; k < 2; k++)
        if (e[k] >= 0) r[k] = atomicAdd(&scnt[e[k]], 1);
    __syncthreads();
    if (t < L_EXP) sbase[t] = (scnt[t] > 0) ? atomicAdd(&g_cursor[t], scnt[t]) : 0;
    __syncthreads();

    #pragma unroll
    for (int k = 0; k < 2; k++) {
        if (e[k] >= 0) {
            const int slot = sbase[e[k]] + r[k];
            if (slot < ((e[k] + 1) << SEG_SHIFT)) {
                g_perm[slot] = p0 + k;
                g_xb[2*slot]   = make_float4(f[7*k],   f[7*k+1], f[7*k+2], f[7*k+3]);
                g_xb[2*slot+1] = make_float4(f[7*k+4], f[7*k+5], f[7*k+6], 0.f);
            }
        }
    }

    // ---- tail: last block snapshots counts, resets cursors, builds work list ----
    if (t == 0) {
        __threadfence();
        s_last = (atomicAdd(&g_done, 1) == nblk - 1) ? 1 : 0;
    }
    __syncthreads();
    if (s_last) {
        if (t < L_EXP) {
            int c = g_cursor[t] - (t << SEG_SHIFT);
            if (c > SEG) c = SEG;
            g_cnt[t] = c;
            g_cursor[t] = t << SEG_SHIFT;
            s_pref[t] = (c + PPB - 1) / PPB;
        }
        __syncthreads();
        if (t == 0) {
            int acc = 0;
            #pragma unroll
            for (int k = 0; k < L_EXP; k++) { int nb = s_pref[k]; s_pref[k] = acc; acc += nb; }
            s_pref[L_EXP] = acc;
            g_nwork = acc;
            g_done = 0;
        }
        __syncthreads();
        if (t < L_EXP) {
            const int start = s_pref[t];
            const int nb    = s_pref[t + 1] - start;
            for (int b = 0; b < nb; b++) g_work[start + b] = (t << 8) | b;
        }
    }
}

// ---------------- pass 2: block-uniform-expert MLP, 2 pts/thread (R6 body) ----------------
__global__ __launch_bounds__(TPB)
void k_main(const float* __restrict__ W0, const float* __restrict__ b0,
            const float* __restrict__ W1, const float* __restrict__ b1,
            const float* __restrict__ W2, const float* __restrict__ b2,
            float* __restrict__ out)
{
    __shared__ __align__(16) float sW0[IN0 * C0];
    __shared__ __align__(16) float sW1[C0 * C1];
    __shared__ __align__(16) float sW2[C1 * C2];
    __shared__ __align__(16) float sB0[C0];
    __shared__ __align__(16) float sB1[C1];
    __shared__ __align__(16) float sB2[C2];

    if ((int)blockIdx.x >= g_nwork) return;
    const int w          = g_work[blockIdx.x];
    const int e          = w >> 8;
    const int local_base = (w & 0xff) * PPB;
    const int cnt        = g_cnt[e];

    const int t = threadIdx.x;

    const float* W0e = W0 + e * IN0 * C0;
    const float* W1e = W1 + e * C0 * C1;
    const float* W2e = W2 + e * C1 * C2;
    for (int d = t; d < IN0 * C0; d += TPB) sW0[d] = W0e[d];
    for (int d = t; d < C0 * C1;  d += TPB) sW1[d] = W1e[d];
    for (int d = t; d < C1 * C2;  d += TPB) sW2[d] = W2e[d];
    if (t < C0) sB0[t] = b0[e * C0 + t];
    if (t < C1) sB1[t] = b1[e * C1 + t];
    if (t < C2) sB2[t] = b2[e * C2 + t];
    __syncthreads();

    const int seg0 = (e << SEG_SHIFT) + local_base;
    bool valid[PPT];
    float h0[PPT][8];
    #pragma unroll
    for (int q = 0; q < PPT; q++) {
        valid[q] = (local_base + t + q * TPB) < cnt;
        const int slot = seg0 + t + q * TPB;
        if (valid[q]) {
            float4 a = g_xb[2 * slot];
            float4 b = g_xb[2 * slot + 1];
            h0[q][0]=a.x; h0[q][1]=a.y; h0[q][2]=a.z; h0[q][3]=a.w;
            h0[q][4]=b.x; h0[q][5]=b.y; h0[q][6]=b.z;
        } else {
            #pragma unroll
            for (int i = 0; i < 7; i++) h0[q][i] = 0.f;
        }
    }

    // ---- layer 0: 7 -> 16 ----
    float2 a0[PPT][C0 / 2];
    #pragma unroll
    for (int o = 0; o < C0 / 2; o++) {
        float2 bv = ((const float2*)sB0)[o];
        a0[0][o] = bv; a0[1][o] = bv;
    }
    #pragma unroll
    for (int i = 0; i < IN0; i++) {
        float2 hA = make_float2(h0[0][i], h0[0][i]);
        float2 hB = make_float2(h0[1][i], h0[1][i]);
        #pragma unroll
        for (int q4 = 0; q4 < C0 / 4; q4++) {
            float4 w4 = *(const float4*)&sW0[i * C0 + 4 * q4];
            float2 w01 = make_float2(w4.x, w4.y), w23 = make_float2(w4.z, w4.w);
            a0[0][2*q4]   = ffma2(hA, w01, a0[0][2*q4]);
            a0[0][2*q4+1] = ffma2(hA, w23, a0[0][2*q4+1]);
            a0[1][2*q4]   = ffma2(hB, w01, a0[1][2*q4]);
            a0[1][2*q4+1] = ffma2(hB, w23, a0[1][2*q4+1]);
        }
    }
    float h1[PPT][C0];
    #pragma unroll
    for (int q = 0; q < PPT; q++)
        #pragma unroll
        for (int o = 0; o < C0 / 2; o++) {
            h1[q][2*o]   = lrelu(a0[q][o].x);
            h1[q][2*o+1] = lrelu(a0[q][o].y);
        }

    // ---- layer 1: 16 -> 32 ----
    float2 a1[PPT][C1 / 2];
    #pragma unroll
    for (int o = 0; o < C1 / 2; o++) {
        float2 bv = ((const float2*)sB1)[o];
        a1[0][o] = bv; a1[1][o] = bv;
    }
    #pragma unroll
    for (int i = 0; i < C0; i++) {
        float2 hA = make_float2(h1[0][i], h1[0][i]);
        float2 hB = make_float2(h1[1][i], h1[1][i]);
        #pragma unroll
        for (int q4 = 0; q4 < C1 / 4; q4++) {
            float4 w4 = *(const float4*)&sW1[i * C1 + 4 * q4];
            float2 w01 = make_float2(w4.x, w4.y), w23 = make_float2(w4.z, w4.w);
            a1[0][2*q4]   = ffma2(hA, w01, a1[0][2*q4]);
            a1[0][2*q4+1] = ffma2(hA, w23, a1[0][2*q4+1]);
            a1[1][2*q4]   = ffma2(hB, w01, a1[1][2*q4]);
            a1[1][2*q4+1] = ffma2(hB, w23, a1[1][2*q4+1]);
        }
    }
    float h2[PPT][C1];
    #pragma unroll
    for (int q = 0; q < PPT; q++)
        #pragma unroll
        for (int o = 0; o < C1 / 2; o++) {
            h2[q][2*o]   = lrelu(a1[q][o].x);
            h2[q][2*o+1] = lrelu(a1[q][o].y);
        }

    // ---- layer 2: 32 -> 16 ----
    float2 a2[PPT][C2 / 2];
    #pragma unroll
    for (int o = 0; o < C2 / 2; o++) {
        float2 bv = ((const float2*)sB2)[o];
        a2[0][o] = bv; a2[1][o] = bv;
    }
    #pragma unroll
    for (int i = 0; i < C1; i++) {
        float2 hA = make_float2(h2[0][i], h2[0][i]);
        float2 hB = make_float2(h2[1][i], h2[1][i]);
        #pragma unroll
        for (int q4 = 0; q4 < C2 / 4; q4++) {
            float4 w4 = *(const float4*)&sW2[i * C2 + 4 * q4];
            float2 w01 = make_float2(w4.x, w4.y), w23 = make_float2(w4.z, w4.w);
            a2[0][2*q4]   = ffma2(hA, w01, a2[0][2*q4]);
            a2[0][2*q4+1] = ffma2(hA, w23, a2[0][2*q4+1]);
            a2[1][2*q4]   = ffma2(hB, w01, a2[1][2*q4]);
            a2[1][2*q4+1] = ffma2(hB, w23, a2[1][2*q4+1]);
        }
    }

    #pragma unroll
    for (int q = 0; q < PPT; q++) {
        if (valid[q]) {
            const int p = g_perm[seg0 + t + q * TPB];
            float ho[C2];
            #pragma unroll
            for (int o = 0; o < C2 / 2; o++) {
                ho[2*o]   = lrelu(a2[q][o].x);
                ho[2*o+1] = lrelu(a2[q][o].y);
            }
            float4* op = reinterpret_cast<float4*>(out + (size_t)p * C2);
            op[0] = make_float4(ho[0],  ho[1],  ho[2],  ho[3]);
            op[1] = make_float4(ho[4],  ho[5],  ho[6],  ho[7]);
            op[2] = make_float4(ho[8],  ho[9],  ho[10], ho[11]);
            op[3] = make_float4(ho[12], ho[13], ho[14], ho[15]);
        }
    }
}

extern "C" void kernel_launch(void* const* d_in, const int* in_sizes, int n_in,
                              void* d_out, int out_size)
{
    const float* x   = (const float*)d_in[0];
    const int*   idx = (const int*)  d_in[1];
    const float* W0  = (const float*)d_in[2];
    const float* b0  = (const float*)d_in[3];
    const float* W1  = (const float*)d_in[4];
    const float* b1  = (const float*)d_in[5];
    const float* W2  = (const float*)d_in[6];
    const float* b2  = (const float*)d_in[7];
    float* out = (float*)d_out;

    const int n = in_sizes[1];

    const int nblk_s = (n + 2 * TPB - 1) / (2 * TPB);
    k_scatter<<<nblk_s, TPB>>>(idx, x, n, nblk_s);

    int maxwork = (n + PPB - 1) / PPB + L_EXP;
    if (maxwork > WORK_CAP) maxwork = WORK_CAP;
    k_main<<<maxwork, TPB>>>(W0, b0, W1, b1, W2, b2, out);
}